// round 3
// baseline (speedup 1.0000x reference)
#include <cuda_runtime.h>
#include <math.h>

#define Bv 16384
#define Dv 256
#define Ev 8
#define Hv 128
#define NB 18            // blocks per expert -> 144 total (one wave on 148 SMs)
#define NT 32            // tokens per tile
#define TPB 512          // 16 warps -> 4 warps/SMSP

// packed f32x2 FMA: 2 fp32 FMAs per issue slot (sm_103a)
#define FMA2(c, a, b) \
    asm("fma.rn.f32x2 %0, %1, %2, %0;" : "+l"(c) : "l"(a), "l"(b))
#define UNPACK2(lo, hi, v) \
    asm("mov.b64 {%0, %1}, %2;" : "=f"(lo), "=f"(hi) : "l"(v))

// ---------------- scratch (no allocations allowed) ----------------
__device__ int   g_count[Ev];
__device__ int   g_tok[Ev][Bv];
__device__ float g_w[Ev][Bv];

// ---------------- kernel 0: zero counters ----------------
__global__ void k_zero() {
    if (threadIdx.x < Ev) g_count[threadIdx.x] = 0;
}

// ---------------- kernel 1: gating (softmax + top-2) + zero out ----------
__global__ void __launch_bounds__(256) k_gate(const float* __restrict__ feat,
                                              const float* __restrict__ Wg,
                                              float* __restrict__ out) {
    __shared__ float WgT[Ev * 256];   // WgT[e*256 + d]
    for (int i = threadIdx.x; i < Dv * Ev; i += 256) {
        int d = i >> 3, e = i & 7;
        WgT[e * 256 + d] = Wg[i];
    }
    __syncthreads();

    int w = threadIdx.x >> 5, l = threadIdx.x & 31;
    int tok = blockIdx.x * 8 + w;
    if (l == 0) out[tok] = 0.f;      // zero output for later atomics
    const float* x = feat + (size_t)tok * Dv;

    float acc[Ev];
#pragma unroll
    for (int e = 0; e < Ev; e++) acc[e] = 0.f;

#pragma unroll
    for (int d0 = 0; d0 < Dv; d0 += 128) {
        float4 x4 = *(const float4*)(x + d0 + l * 4);
#pragma unroll
        for (int e = 0; e < Ev; e++) {
            const float* wr = WgT + e * 256 + d0 + l * 4;
            acc[e] += x4.x * wr[0];
            acc[e] += x4.y * wr[1];
            acc[e] += x4.z * wr[2];
            acc[e] += x4.w * wr[3];
        }
    }
#pragma unroll
    for (int e = 0; e < Ev; e++) {
#pragma unroll
        for (int off = 16; off; off >>= 1)
            acc[e] += __shfl_down_sync(0xffffffffu, acc[e], off);
    }

    if (l == 0) {
        float m = acc[0];
#pragma unroll
        for (int e = 1; e < Ev; e++) m = fmaxf(m, acc[e]);
        float g[Ev];
        float sum = 0.f;
#pragma unroll
        for (int e = 0; e < Ev; e++) { g[e] = expf(acc[e] - m); sum += g[e]; }
        float inv = 1.f / sum;
#pragma unroll
        for (int e = 0; e < Ev; e++) g[e] *= inv;

        int i0 = 0;
#pragma unroll
        for (int e = 1; e < Ev; e++) if (g[e] > g[i0]) i0 = e;
        int i1 = -1;
#pragma unroll
        for (int e = 0; e < Ev; e++) {
            if (e == i0) continue;
            if (i1 < 0 || g[e] > g[i1]) i1 = e;
        }
        float denom = g[i0] + g[i1] + 1e-10f;
        float w0 = g[i0] / denom, w1 = g[i1] / denom;

        int r0 = atomicAdd(&g_count[i0], 1);
        g_tok[i0][r0] = tok; g_w[i0][r0] = w0;
        int r1 = atomicAdd(&g_count[i1], 1);
        g_tok[i1][r1] = tok; g_w[i1][r1] = w1;
    }
}

// ---------------- kernel 2: expert compute ----------------
// smem layout (floats), XOR-swizzled weight tiles (no padding):
//   W1t [128][256] : 0      (W1t[h*256 + (d ^ ((h&7)<<2))] = W1[e][d][h])
//   Wpt [128][128] : 32768  (Wpt[k*128 + (h ^ ((k&7)<<2))] = Wp[e][h][k])
//   xs  [32][256]  : 49152  (cs [32][128] ALIASES xs after phase A)
//   Wo_s[128]      : 57344
//   b1_s[128]      : 57472
//   bp_s[128]      : 57600
//   red [64]       : 57728
//   tk  [32] int   : 57792
//   wt  [32]       : 57824
// total 57856 floats = 231424 bytes
#define SMEM_BYTES (57856 * 4)

__global__ void __launch_bounds__(TPB, 1) k_expert(
    const float* __restrict__ feat,
    const float* __restrict__ W1, const float* __restrict__ b1,
    const float* __restrict__ Wp, const float* __restrict__ bp,
    const float* __restrict__ mix_logit,
    const float* __restrict__ Wo, const float* __restrict__ bo,
    float* __restrict__ out)
{
    extern __shared__ float sm[];
    float* W1t  = sm;
    float* Wpt  = sm + 32768;
    float* xs   = sm + 49152;
    float* cs   = sm + 49152;          // alias, used after phase A
    float* Wo_s = sm + 57344;
    float* b1_s = sm + 57472;
    float* bp_s = sm + 57600;
    float* red  = sm + 57728;
    int*   tk   = (int*)(sm + 57792);
    float* wt   = sm + 57824;

    const int e   = blockIdx.x & 7;
    const int j   = blockIdx.x >> 3;
    const int tid = threadIdx.x;

    // stage weights into smem with XOR swizzle
    for (int i = tid; i < Dv * Hv; i += TPB) {
        int d = i >> 7, h = i & 127;
        W1t[h * 256 + (d ^ ((h & 7) << 2))] = W1[e * Dv * Hv + i];
    }
    for (int i = tid; i < Hv * Hv; i += TPB) {
        int h = i >> 7, k = i & 127;
        Wpt[k * 128 + (h ^ ((k & 7) << 2))] = Wp[e * Hv * Hv + i];
    }
    if (tid < Hv) {
        Wo_s[tid] = Wo[e * Hv + tid];
        b1_s[tid] = b1[e * Hv + tid];
        bp_s[tid] = bp[e * Hv + tid];
    }
    const float mix  = 1.f / (1.f + expf(-mix_logit[e]));
    const float omix = 1.f - mix;
    const float boe  = bo[e];
    const int   n    = g_count[e];
    __syncthreads();

    // layout: 64 h-slots (RH=2: h0, h0+64) x 8 token-groups (RT=4 tokens each)
    const int h0  = tid & 63;
    const int h1  = h0 + 64;
    const int s   = tid >> 6;          // 0..7
    const int wig = (tid >> 5) & 1;
    const int sw  = (h0 & 7) << 2;     // same for h1 (h1&7 == h0&7)

    const float* wr0 = W1t + h0 * 256;
    const float* wr1 = W1t + h1 * 256;
    const float* pr0 = Wpt + h0 * 128;
    const float* pr1 = Wpt + h1 * 128;
    const float wo0 = Wo_s[h0], wo1 = Wo_s[h1];
    const float b10 = b1_s[h0], b11 = b1_s[h1];
    const float bb0 = bp_s[h0], bb1 = bp_s[h1];

    const int* tok_list = g_tok[e];

    for (int base = j * NT; base < n; base += NB * NT) {
        const int nt = min(NT, n - base);
        // gather features (token ids read straight from gmem, L1-resident)
        for (int i = tid; i < nt * 64; i += TPB) {
            int t = i >> 6, q = i & 63;
            int token = tok_list[base + t];
            *(float4*)(xs + t * 256 + q * 4) =
                *(const float4*)(feat + (size_t)token * Dv + q * 4);
        }
        if (tid < nt) {
            tk[tid] = tok_list[base + tid];
            wt[tid] = g_w[e][base + tid];
        }
        __syncthreads();

        // ---- phase A: core = relu(x @ W1 + b1) ----
        unsigned long long a0[4], a1[4];
#pragma unroll
        for (int t = 0; t < 4; t++) { a0[t] = 0ull; a1[t] = 0ull; }
        {
            const float* xb = xs + (s << 2) * 256;
#pragma unroll 4
            for (int d4 = 0; d4 < 256; d4 += 4) {
                int dsw = d4 ^ sw;
                ulonglong2 wa = *(const ulonglong2*)(wr0 + dsw);
                ulonglong2 wb = *(const ulonglong2*)(wr1 + dsw);
#pragma unroll
                for (int t = 0; t < 4; t++) {
                    ulonglong2 xv = *(const ulonglong2*)(xb + t * 256 + d4);
                    FMA2(a0[t], wa.x, xv.x);
                    FMA2(a0[t], wa.y, xv.y);
                    FMA2(a1[t], wb.x, xv.x);
                    FMA2(a1[t], wb.y, xv.y);
                }
            }
        }
        float c0[4], c1[4];
#pragma unroll
        for (int t = 0; t < 4; t++) {
            float lo, hi;
            UNPACK2(lo, hi, a0[t]);
            c0[t] = fmaxf(lo + hi + b10, 0.f);
            UNPACK2(lo, hi, a1[t]);
            c1[t] = fmaxf(lo + hi + b11, 0.f);
        }
        __syncthreads();     // all reads of xs done -> safe to overwrite with cs
#pragma unroll
        for (int t = 0; t < 4; t++) {
            int tt = (s << 2) + t;
            cs[tt * 128 + h0] = c0[t];
            cs[tt * 128 + h1] = c1[t];
        }
        __syncthreads();

        // ---- phase B: plast = tanh(core @ Wp + bp); fuse mix + Wo projection ----
#pragma unroll
        for (int t = 0; t < 4; t++) { a0[t] = 0ull; a1[t] = 0ull; }
        {
            const float* cb = cs + (s << 2) * 128;
#pragma unroll 4
            for (int h4 = 0; h4 < 128; h4 += 4) {
                int hsw = h4 ^ sw;
                ulonglong2 wa = *(const ulonglong2*)(pr0 + hsw);
                ulonglong2 wb = *(const ulonglong2*)(pr1 + hsw);
#pragma unroll
                for (int t = 0; t < 4; t++) {
                    ulonglong2 cv = *(const ulonglong2*)(cb + t * 128 + h4);
                    FMA2(a0[t], wa.x, cv.x);
                    FMA2(a0[t], wa.y, cv.y);
                    FMA2(a1[t], wb.x, cv.x);
                    FMA2(a1[t], wb.y, cv.y);
                }
            }
        }
#pragma unroll
        for (int t = 0; t < 4; t++) {
            float lo, hi;
            UNPACK2(lo, hi, a0[t]);
            float p0 = tanhf(lo + hi + bb0);
            UNPACK2(lo, hi, a1[t]);
            float p1 = tanhf(lo + hi + bb1);
            float p = (omix * c0[t] + mix * p0) * wo0
                    + (omix * c1[t] + mix * p1) * wo1;
#pragma unroll
            for (int off = 16; off; off >>= 1)
                p += __shfl_down_sync(0xffffffffu, p, off);
            if ((tid & 31) == 0) red[((s << 2) + t) * 2 + wig] = p;
        }
        __syncthreads();

        if (tid < nt) {
            float val = wt[tid] * (red[tid * 2] + red[tid * 2 + 1] + boe);
            atomicAdd(&out[tk[tid]], val);
        }
        __syncthreads();
    }
}

// ---------------- launcher ----------------
extern "C" void kernel_launch(void* const* d_in, const int* in_sizes, int n_in,
                              void* d_out, int out_size) {
    const float* feat      = (const float*)d_in[0];
    const float* Wg        = (const float*)d_in[1];
    const float* W1        = (const float*)d_in[2];
    const float* b1        = (const float*)d_in[3];
    const float* Wp        = (const float*)d_in[4];
    const float* bp        = (const float*)d_in[5];
    const float* mix_logit = (const float*)d_in[6];
    const float* Wo        = (const float*)d_in[7];
    const float* bo        = (const float*)d_in[8];
    float* out = (float*)d_out;

    cudaFuncSetAttribute(k_expert, cudaFuncAttributeMaxDynamicSharedMemorySize,
                         SMEM_BYTES);

    k_zero<<<1, 32>>>();
    k_gate<<<Bv / 8, 256>>>(feat, Wg, out);
    k_expert<<<NB * Ev, TPB, SMEM_BYTES>>>(feat, W1, b1, Wp, bp, mix_logit,
                                           Wo, bo, out);
}

// round 4
// speedup vs baseline: 1.0952x; 1.0952x over previous
#include <cuda_runtime.h>
#include <math.h>

#define Bv 16384
#define Dv 256
#define Ev 8
#define Hv 128
#define NB 18            // blocks per expert -> 144 total (one wave on 148 SMs)
#define NT 32            // tokens per tile

// packed f32x2 FMA: 2 fp32 FMAs per issue slot (sm_103a)
#define FMA2(c, a, b) \
    asm("fma.rn.f32x2 %0, %1, %2, %0;" : "+l"(c) : "l"(a), "l"(b))
#define UNPACK2(lo, hi, v) \
    asm("mov.b64 {%0, %1}, %2;" : "=f"(lo), "=f"(hi) : "l"(v))

// ---------------- scratch (no allocations allowed) ----------------
__device__ int   g_count[Ev];
__device__ int   g_tok[Ev][Bv];
__device__ float g_w[Ev][Bv];

// ---------------- kernel 0: zero counters ----------------
__global__ void k_zero() {
    if (threadIdx.x < Ev) g_count[threadIdx.x] = 0;
}

// ---------------- kernel 1: gating (softmax + top-2) + zero out ----------
__global__ void __launch_bounds__(256) k_gate(const float* __restrict__ feat,
                                              const float* __restrict__ Wg,
                                              float* __restrict__ out) {
    __shared__ float WgT[Ev * 256];   // WgT[e*256 + d]
    for (int i = threadIdx.x; i < Dv * Ev; i += 256) {
        int d = i >> 3, e = i & 7;
        WgT[e * 256 + d] = Wg[i];
    }
    __syncthreads();

    int w = threadIdx.x >> 5, l = threadIdx.x & 31;
    int tok = blockIdx.x * 8 + w;
    if (l == 0) out[tok] = 0.f;      // zero output for later atomics
    const float* x = feat + (size_t)tok * Dv;

    float acc[Ev];
#pragma unroll
    for (int e = 0; e < Ev; e++) acc[e] = 0.f;

#pragma unroll
    for (int d0 = 0; d0 < Dv; d0 += 128) {
        float4 x4 = *(const float4*)(x + d0 + l * 4);
#pragma unroll
        for (int e = 0; e < Ev; e++) {
            const float* wr = WgT + e * 256 + d0 + l * 4;
            acc[e] += x4.x * wr[0];
            acc[e] += x4.y * wr[1];
            acc[e] += x4.z * wr[2];
            acc[e] += x4.w * wr[3];
        }
    }
#pragma unroll
    for (int e = 0; e < Ev; e++) {
#pragma unroll
        for (int off = 16; off; off >>= 1)
            acc[e] += __shfl_down_sync(0xffffffffu, acc[e], off);
    }

    if (l == 0) {
        float m = acc[0];
#pragma unroll
        for (int e = 1; e < Ev; e++) m = fmaxf(m, acc[e]);
        float g[Ev];
        float sum = 0.f;
#pragma unroll
        for (int e = 0; e < Ev; e++) { g[e] = expf(acc[e] - m); sum += g[e]; }
        float inv = 1.f / sum;
#pragma unroll
        for (int e = 0; e < Ev; e++) g[e] *= inv;

        int i0 = 0;
#pragma unroll
        for (int e = 1; e < Ev; e++) if (g[e] > g[i0]) i0 = e;
        int i1 = -1;
#pragma unroll
        for (int e = 0; e < Ev; e++) {
            if (e == i0) continue;
            if (i1 < 0 || g[e] > g[i1]) i1 = e;
        }
        float denom = g[i0] + g[i1] + 1e-10f;
        float w0 = g[i0] / denom, w1 = g[i1] / denom;

        int r0 = atomicAdd(&g_count[i0], 1);
        g_tok[i0][r0] = tok; g_w[i0][r0] = w0;
        int r1 = atomicAdd(&g_count[i1], 1);
        g_tok[i1][r1] = tok; g_w[i1][r1] = w1;
    }
}

// ---------------- kernel 2: expert compute ----------------
// smem layout (floats), XOR-swizzled weight tiles (no padding):
//   W1t [128][256] : 0      (W1t[h*256 + (d ^ ((h&7)<<2))] = W1[e][d][h])
//   Wpt [128][128] : 32768  (Wpt[k*128 + (h ^ ((k&7)<<2))] = Wp[e][h][k])
//   xs  [32][256]  : 49152  (cs [32][128] ALIASES xs after phase A)
//   Wo_s[128]      : 57344
//   b1_s[128]      : 57472
//   bp_s[128]      : 57600
//   red [64]       : 57728
//   tk  [32] int   : 57792
//   wt  [32]       : 57824
// total 57856 floats = 231424 bytes
#define SMEM_BYTES (57856 * 4)

__global__ void __launch_bounds__(256, 1) k_expert(
    const float* __restrict__ feat,
    const float* __restrict__ W1, const float* __restrict__ b1,
    const float* __restrict__ Wp, const float* __restrict__ bp,
    const float* __restrict__ mix_logit,
    const float* __restrict__ Wo, const float* __restrict__ bo,
    float* __restrict__ out)
{
    extern __shared__ float sm[];
    float* W1t  = sm;
    float* Wpt  = sm + 32768;
    float* xs   = sm + 49152;
    float* cs   = sm + 49152;          // alias, used after phase A
    float* Wo_s = sm + 57344;
    float* b1_s = sm + 57472;
    float* bp_s = sm + 57600;
    float* red  = sm + 57728;
    int*   tk   = (int*)(sm + 57792);
    float* wt   = sm + 57824;

    const int e   = blockIdx.x & 7;
    const int j   = blockIdx.x >> 3;
    const int tid = threadIdx.x;

    // stage weights into smem with XOR swizzle
    for (int i = tid; i < Dv * Hv; i += 256) {
        int d = i >> 7, h = i & 127;
        W1t[h * 256 + (d ^ ((h & 7) << 2))] = W1[e * Dv * Hv + i];
    }
    for (int i = tid; i < Hv * Hv; i += 256) {
        int h = i >> 7, k = i & 127;
        Wpt[k * 128 + (h ^ ((k & 7) << 2))] = Wp[e * Hv * Hv + i];
    }
    if (tid < Hv) {
        Wo_s[tid] = Wo[e * Hv + tid];
        b1_s[tid] = b1[e * Hv + tid];
        bp_s[tid] = bp[e * Hv + tid];
    }
    const float mix  = 1.f / (1.f + expf(-mix_logit[e]));
    const float omix = 1.f - mix;
    const float boe  = bo[e];
    const int   n    = g_count[e];
    __syncthreads();

    // layout: 64 h-slots (RH=2: h0, h0+64) x 4 token-groups (RT=8 tokens each)
    const int h0  = tid & 63;
    const int h1  = h0 + 64;
    const int s   = tid >> 6;
    const int wig = (tid >> 5) & 1;
    const int sw  = (h0 & 7) << 2;     // same for h1 (h1&7 == h0&7)

    const float* wr0 = W1t + h0 * 256;
    const float* wr1 = W1t + h1 * 256;
    const float* pr0 = Wpt + h0 * 128;
    const float* pr1 = Wpt + h1 * 128;
    const float wo0 = Wo_s[h0], wo1 = Wo_s[h1];
    const float b10 = b1_s[h0], b11 = b1_s[h1];
    const float bb0 = bp_s[h0], bb1 = bp_s[h1];

    const int* tok_list = g_tok[e];
    const int tq = tid & 63;           // float4 column within a token row
    const int tt0 = tid >> 6;          // base token index handled by this thread

    // ---- prefetch first tile into registers ----
    float4 pf[8];
    int base = j * NT;
    if (base < n) {
#pragma unroll
        for (int k = 0; k < 8; k++) {
            int t = tt0 + 4 * k;
            int idx = min(base + t, n - 1);
            pf[k] = *(const float4*)(feat + (size_t)tok_list[idx] * Dv + tq * 4);
        }
    }

    for (; base < n; base += NB * NT) {
        const int nt = min(NT, n - base);
        // dump prefetched tile to smem
#pragma unroll
        for (int k = 0; k < 8; k++) {
            int t = tt0 + 4 * k;
            *(float4*)(xs + t * 256 + tq * 4) = pf[k];
        }
        if (tid < NT) {
            int idx = min(base + tid, n - 1);
            tk[tid] = tok_list[idx];
            wt[tid] = g_w[e][idx];
        }
        __syncthreads();

        // ---- issue prefetch for NEXT tile (flies during compute) ----
        const int nbase = base + NB * NT;
        if (nbase < n) {
#pragma unroll
            for (int k = 0; k < 8; k++) {
                int t = tt0 + 4 * k;
                int idx = min(nbase + t, n - 1);
                pf[k] = *(const float4*)(feat + (size_t)tok_list[idx] * Dv + tq * 4);
            }
        }

        // ---- phase A: core = relu(x @ W1 + b1) ----
        unsigned long long a0[8], a1[8];
#pragma unroll
        for (int t = 0; t < 8; t++) { a0[t] = 0ull; a1[t] = 0ull; }
        {
            const float* xb = xs + (s << 3) * 256;
#pragma unroll 4
            for (int d4 = 0; d4 < 256; d4 += 4) {
                int dsw = d4 ^ sw;
                ulonglong2 wa = *(const ulonglong2*)(wr0 + dsw);
                ulonglong2 wb = *(const ulonglong2*)(wr1 + dsw);
#pragma unroll
                for (int t = 0; t < 8; t++) {
                    ulonglong2 xv = *(const ulonglong2*)(xb + t * 256 + d4);
                    FMA2(a0[t], wa.x, xv.x);
                    FMA2(a0[t], wa.y, xv.y);
                    FMA2(a1[t], wb.x, xv.x);
                    FMA2(a1[t], wb.y, xv.y);
                }
            }
        }
        float c0[8], c1[8];
#pragma unroll
        for (int t = 0; t < 8; t++) {
            float lo, hi;
            UNPACK2(lo, hi, a0[t]);
            c0[t] = fmaxf(lo + hi + b10, 0.f);
            UNPACK2(lo, hi, a1[t]);
            c1[t] = fmaxf(lo + hi + b11, 0.f);
        }
        __syncthreads();     // all reads of xs done -> safe to overwrite with cs
#pragma unroll
        for (int t = 0; t < 8; t++) {
            int tt = (s << 3) + t;
            cs[tt * 128 + h0] = c0[t];
            cs[tt * 128 + h1] = c1[t];
        }
        __syncthreads();

        // ---- phase B: plast = tanh(core @ Wp + bp); fuse mix + Wo projection ----
#pragma unroll
        for (int t = 0; t < 8; t++) { a0[t] = 0ull; a1[t] = 0ull; }
        {
            const float* cb = cs + (s << 3) * 128;
#pragma unroll 4
            for (int h4 = 0; h4 < 128; h4 += 4) {
                int hsw = h4 ^ sw;
                ulonglong2 wa = *(const ulonglong2*)(pr0 + hsw);
                ulonglong2 wb = *(const ulonglong2*)(pr1 + hsw);
#pragma unroll
                for (int t = 0; t < 8; t++) {
                    ulonglong2 cv = *(const ulonglong2*)(cb + t * 128 + h4);
                    FMA2(a0[t], wa.x, cv.x);
                    FMA2(a0[t], wa.y, cv.y);
                    FMA2(a1[t], wb.x, cv.x);
                    FMA2(a1[t], wb.y, cv.y);
                }
            }
        }
#pragma unroll
        for (int t = 0; t < 8; t++) {
            float lo, hi;
            UNPACK2(lo, hi, a0[t]);
            float p0 = tanhf(lo + hi + bb0);
            UNPACK2(lo, hi, a1[t]);
            float p1 = tanhf(lo + hi + bb1);
            float p = (omix * c0[t] + mix * p0) * wo0
                    + (omix * c1[t] + mix * p1) * wo1;
#pragma unroll
            for (int off = 16; off; off >>= 1)
                p += __shfl_down_sync(0xffffffffu, p, off);
            if ((tid & 31) == 0) red[((s << 3) + t) * 2 + wig] = p;
        }
        __syncthreads();     // red ready; also: all cs reads done -> xs reusable

        if (tid < nt) {
            float val = wt[tid] * (red[tid * 2] + red[tid * 2 + 1] + boe);
            atomicAdd(&out[tk[tid]], val);
        }
        // no extra sync: next-iteration xs stores are ordered by the sync above
        // for cs readers; tk/wt rewrite only touches tid<NT which also did the
        // atomic in program order, and other threads' xs stores don't touch red.
        __syncthreads();
    }
}

// ---------------- launcher ----------------
extern "C" void kernel_launch(void* const* d_in, const int* in_sizes, int n_in,
                              void* d_out, int out_size) {
    const float* feat      = (const float*)d_in[0];
    const float* Wg        = (const float*)d_in[1];
    const float* W1        = (const float*)d_in[2];
    const float* b1        = (const float*)d_in[3];
    const float* Wp        = (const float*)d_in[4];
    const float* bp        = (const float*)d_in[5];
    const float* mix_logit = (const float*)d_in[6];
    const float* Wo        = (const float*)d_in[7];
    const float* bo        = (const float*)d_in[8];
    float* out = (float*)d_out;

    cudaFuncSetAttribute(k_expert, cudaFuncAttributeMaxDynamicSharedMemorySize,
                         SMEM_BYTES);

    k_zero<<<1, 32>>>();
    k_gate<<<Bv / 8, 256>>>(feat, Wg, out);
    k_expert<<<NB * Ev, 256, SMEM_BYTES>>>(feat, W1, b1, Wp, bp, mix_logit,
                                           Wo, bo, out);
}

// round 5
// speedup vs baseline: 1.0987x; 1.0032x over previous
#include <cuda_runtime.h>
#include <math.h>

#define Bv 16384
#define Dv 256
#define Ev 8
#define Hv 128
#define NB 18            // blocks per expert -> 144 total (one wave on 148 SMs)
#define NT 32            // tokens per tile

// packed f32x2 FMA: 2 fp32 FMAs per issue slot (sm_103a)
#define FMA2(c, a, b) \
    asm("fma.rn.f32x2 %0, %1, %2, %0;" : "+l"(c) : "l"(a), "l"(b))
#define UNPACK2(lo, hi, v) \
    asm("mov.b64 {%0, %1}, %2;" : "=f"(lo), "=f"(hi) : "l"(v))

// ---------------- scratch (no allocations allowed) ----------------
__device__ int   g_count[Ev];
__device__ int   g_tok[Ev][Bv];
__device__ float g_w[Ev][Bv];

// ---------------- kernel 0: zero counters ----------------
__global__ void k_zero() {
    if (threadIdx.x < Ev) g_count[threadIdx.x] = 0;
}

// ---------------- kernel 1: gating (softmax + top-2) + zero out ----------
__global__ void __launch_bounds__(256) k_gate(const float* __restrict__ feat,
                                              const float* __restrict__ Wg,
                                              float* __restrict__ out) {
    __shared__ float WgT[Ev * 256];   // WgT[e*256 + d]
    for (int i = threadIdx.x; i < Dv * Ev; i += 256) {
        int d = i >> 3, e = i & 7;
        WgT[e * 256 + d] = Wg[i];
    }
    __syncthreads();

    int w = threadIdx.x >> 5, l = threadIdx.x & 31;
    int tok = blockIdx.x * 8 + w;
    if (l == 0) out[tok] = 0.f;      // zero output for later atomics
    const float* x = feat + (size_t)tok * Dv;

    float acc[Ev];
#pragma unroll
    for (int e = 0; e < Ev; e++) acc[e] = 0.f;

#pragma unroll
    for (int d0 = 0; d0 < Dv; d0 += 128) {
        float4 x4 = *(const float4*)(x + d0 + l * 4);
#pragma unroll
        for (int e = 0; e < Ev; e++) {
            const float* wr = WgT + e * 256 + d0 + l * 4;
            acc[e] += x4.x * wr[0];
            acc[e] += x4.y * wr[1];
            acc[e] += x4.z * wr[2];
            acc[e] += x4.w * wr[3];
        }
    }
#pragma unroll
    for (int e = 0; e < Ev; e++) {
#pragma unroll
        for (int off = 16; off; off >>= 1)
            acc[e] += __shfl_down_sync(0xffffffffu, acc[e], off);
    }

    if (l == 0) {
        float m = acc[0];
#pragma unroll
        for (int e = 1; e < Ev; e++) m = fmaxf(m, acc[e]);
        float g[Ev];
        float sum = 0.f;
#pragma unroll
        for (int e = 0; e < Ev; e++) { g[e] = expf(acc[e] - m); sum += g[e]; }
        float inv = 1.f / sum;
#pragma unroll
        for (int e = 0; e < Ev; e++) g[e] *= inv;

        int i0 = 0;
#pragma unroll
        for (int e = 1; e < Ev; e++) if (g[e] > g[i0]) i0 = e;
        int i1 = -1;
#pragma unroll
        for (int e = 0; e < Ev; e++) {
            if (e == i0) continue;
            if (i1 < 0 || g[e] > g[i1]) i1 = e;
        }
        float denom = g[i0] + g[i1] + 1e-10f;
        float w0 = g[i0] / denom, w1 = g[i1] / denom;

        int r0 = atomicAdd(&g_count[i0], 1);
        g_tok[i0][r0] = tok; g_w[i0][r0] = w0;
        int r1 = atomicAdd(&g_count[i1], 1);
        g_tok[i1][r1] = tok; g_w[i1][r1] = w1;
    }
}

// ---------------- kernel 2: expert compute ----------------
// smem layout (floats), XOR-swizzled weight tiles (no padding):
//   W1t [128][256] : 0      (W1t[h*256 + (d ^ ((h&7)<<2))] = W1[e][d][h])
//   Wpt [128][128] : 32768  (Wpt[k*128 + (h ^ ((k&7)<<2))] = Wp[e][h][k])
//   xs  [32][256]  : 49152  (cs [32][128] ALIASES xs after phase A)
//   Wo_s[128]      : 57344
//   b1_s[128]      : 57472
//   bp_s[128]      : 57600
//   red [64]       : 57728
//   tk  [32] int   : 57792
//   wt  [32]       : 57824
// total 57856 floats = 231424 bytes
#define SMEM_BYTES (57856 * 4)

__global__ void __launch_bounds__(256, 1) k_expert(
    const float* __restrict__ feat,
    const float* __restrict__ W1, const float* __restrict__ b1,
    const float* __restrict__ Wp, const float* __restrict__ bp,
    const float* __restrict__ mix_logit,
    const float* __restrict__ Wo, const float* __restrict__ bo,
    float* __restrict__ out)
{
    extern __shared__ float sm[];
    float* W1t  = sm;
    float* Wpt  = sm + 32768;
    float* xs   = sm + 49152;
    float* cs   = sm + 49152;          // alias, used after phase A
    float* Wo_s = sm + 57344;
    float* b1_s = sm + 57472;
    float* bp_s = sm + 57600;
    float* red  = sm + 57728;
    int*   tk   = (int*)(sm + 57792);
    float* wt   = sm + 57824;

    const int e   = blockIdx.x & 7;
    const int j   = blockIdx.x >> 3;
    const int tid = threadIdx.x;

    // stage weights into smem with XOR swizzle
    for (int i = tid; i < Dv * Hv; i += 256) {
        int d = i >> 7, h = i & 127;
        W1t[h * 256 + (d ^ ((h & 7) << 2))] = W1[e * Dv * Hv + i];
    }
    for (int i = tid; i < Hv * Hv; i += 256) {
        int h = i >> 7, k = i & 127;
        Wpt[k * 128 + (h ^ ((k & 7) << 2))] = Wp[e * Hv * Hv + i];
    }
    if (tid < Hv) {
        Wo_s[tid] = Wo[e * Hv + tid];
        b1_s[tid] = b1[e * Hv + tid];
        bp_s[tid] = bp[e * Hv + tid];
    }
    const float mix  = 1.f / (1.f + expf(-mix_logit[e]));
    const float omix = 1.f - mix;
    const float boe  = bo[e];
    const int   n    = g_count[e];
    __syncthreads();

    // layout: 64 h-slots (RH=2: h0, h0+64) x 4 token-groups (RT=8 tokens each)
    const int h0  = tid & 63;
    const int h1  = h0 + 64;
    const int s   = tid >> 6;
    const int wig = (tid >> 5) & 1;
    const int sw  = (h0 & 7) << 2;     // same for h1 (h1&7 == h0&7)

    const float* wr0 = W1t + h0 * 256;
    const float* wr1 = W1t + h1 * 256;
    const float* pr0 = Wpt + h0 * 128;
    const float* pr1 = Wpt + h1 * 128;
    const float wo0 = Wo_s[h0], wo1 = Wo_s[h1];
    const float b10 = b1_s[h0], b11 = b1_s[h1];
    const float bb0 = bp_s[h0], bb1 = bp_s[h1];

    const int* tok_list = g_tok[e];
    const int tq = tid & 63;           // float4 column within a token row
    const int tt0 = tid >> 6;          // base token index handled by this thread

    // ---- prefetch first tile into registers ----
    float4 pf[8];
    int base = j * NT;
    if (base < n) {
#pragma unroll
        for (int k = 0; k < 8; k++) {
            int t = tt0 + 4 * k;
            int idx = min(base + t, n - 1);
            pf[k] = *(const float4*)(feat + (size_t)tok_list[idx] * Dv + tq * 4);
        }
    }

    for (; base < n; base += NB * NT) {
        const int nt = min(NT, n - base);
        // dump prefetched tile to smem
#pragma unroll
        for (int k = 0; k < 8; k++) {
            int t = tt0 + 4 * k;
            *(float4*)(xs + t * 256 + tq * 4) = pf[k];
        }
        if (tid < NT) {
            int idx = min(base + tid, n - 1);
            tk[tid] = tok_list[idx];
            wt[tid] = g_w[e][idx];
        }
        __syncthreads();

        // ---- issue prefetch for NEXT tile (flies during compute) ----
        const int nbase = base + NB * NT;
        if (nbase < n) {
#pragma unroll
            for (int k = 0; k < 8; k++) {
                int t = tt0 + 4 * k;
                int idx = min(nbase + t, n - 1);
                pf[k] = *(const float4*)(feat + (size_t)tok_list[idx] * Dv + tq * 4);
            }
        }

        // ---- phase A: core = relu(x @ W1 + b1) ----
        unsigned long long a0[8], a1[8];
#pragma unroll
        for (int t = 0; t < 8; t++) { a0[t] = 0ull; a1[t] = 0ull; }
        {
            const float* xb = xs + (s << 3) * 256;
#pragma unroll 4
            for (int d4 = 0; d4 < 256; d4 += 4) {
                int dsw = d4 ^ sw;
                ulonglong2 wa = *(const ulonglong2*)(wr0 + dsw);
                ulonglong2 wb = *(const ulonglong2*)(wr1 + dsw);
#pragma unroll
                for (int t = 0; t < 8; t++) {
                    ulonglong2 xv = *(const ulonglong2*)(xb + t * 256 + d4);
                    FMA2(a0[t], wa.x, xv.x);
                    FMA2(a0[t], wa.y, xv.y);
                    FMA2(a1[t], wb.x, xv.x);
                    FMA2(a1[t], wb.y, xv.y);
                }
            }
        }
        float c0[8], c1[8];
#pragma unroll
        for (int t = 0; t < 8; t++) {
            float lo, hi;
            UNPACK2(lo, hi, a0[t]);
            c0[t] = fmaxf(lo + hi + b10, 0.f);
            UNPACK2(lo, hi, a1[t]);
            c1[t] = fmaxf(lo + hi + b11, 0.f);
        }
        __syncthreads();     // all reads of xs done -> safe to overwrite with cs
#pragma unroll
        for (int t = 0; t < 8; t++) {
            int tt = (s << 3) + t;
            cs[tt * 128 + h0] = c0[t];
            cs[tt * 128 + h1] = c1[t];
        }
        __syncthreads();

        // ---- phase B: plast = tanh(core @ Wp + bp); fuse mix + Wo projection ----
#pragma unroll
        for (int t = 0; t < 8; t++) { a0[t] = 0ull; a1[t] = 0ull; }
        {
            const float* cb = cs + (s << 3) * 128;
#pragma unroll 4
            for (int h4 = 0; h4 < 128; h4 += 4) {
                int hsw = h4 ^ sw;
                ulonglong2 wa = *(const ulonglong2*)(pr0 + hsw);
                ulonglong2 wb = *(const ulonglong2*)(pr1 + hsw);
#pragma unroll
                for (int t = 0; t < 8; t++) {
                    ulonglong2 cv = *(const ulonglong2*)(cb + t * 128 + h4);
                    FMA2(a0[t], wa.x, cv.x);
                    FMA2(a0[t], wa.y, cv.y);
                    FMA2(a1[t], wb.x, cv.x);
                    FMA2(a1[t], wb.y, cv.y);
                }
            }
        }
#pragma unroll
        for (int t = 0; t < 8; t++) {
            float lo, hi;
            UNPACK2(lo, hi, a0[t]);
            float p0 = tanhf(lo + hi + bb0);
            UNPACK2(lo, hi, a1[t]);
            float p1 = tanhf(lo + hi + bb1);
            float p = (omix * c0[t] + mix * p0) * wo0
                    + (omix * c1[t] + mix * p1) * wo1;
#pragma unroll
            for (int off = 16; off; off >>= 1)
                p += __shfl_down_sync(0xffffffffu, p, off);
            if ((tid & 31) == 0) red[((s << 3) + t) * 2 + wig] = p;
        }
        __syncthreads();     // red ready; also: all cs reads done -> xs reusable

        if (tid < nt) {
            float val = wt[tid] * (red[tid * 2] + red[tid * 2 + 1] + boe);
            atomicAdd(&out[tk[tid]], val);
        }
        // no extra sync: next-iteration xs stores are ordered by the sync above
        // for cs readers; tk/wt rewrite only touches tid<NT which also did the
        // atomic in program order, and other threads' xs stores don't touch red.
        __syncthreads();
    }
}

// ---------------- launcher ----------------
extern "C" void kernel_launch(void* const* d_in, const int* in_sizes, int n_in,
                              void* d_out, int out_size) {
    const float* feat      = (const float*)d_in[0];
    const float* Wg        = (const float*)d_in[1];
    const float* W1        = (const float*)d_in[2];
    const float* b1        = (const float*)d_in[3];
    const float* Wp        = (const float*)d_in[4];
    const float* bp        = (const float*)d_in[5];
    const float* mix_logit = (const float*)d_in[6];
    const float* Wo        = (const float*)d_in[7];
    const float* bo        = (const float*)d_in[8];
    float* out = (float*)d_out;

    cudaFuncSetAttribute(k_expert, cudaFuncAttributeMaxDynamicSharedMemorySize,
                         SMEM_BYTES);

    k_zero<<<1, 32>>>();
    k_gate<<<Bv / 8, 256>>>(feat, Wg, out);
    k_expert<<<NB * Ev, 256, SMEM_BYTES>>>(feat, W1, b1, Wp, bp, mix_logit,
                                           Wo, bo, out);
}